// round 3
// baseline (speedup 1.0000x reference)
#include <cuda_runtime.h>
#include <cuda_bf16.h>

// word_vecs [B=2048, S=200, D=300] fp32 -> masked mean over S -> [B, D].
// All-zero words contribute 0 to the sum, so only the COUNT needs the mask.
//
// Occupancy was grid-limited (2048 CTAs x 3 warps = 65% warp-slot fill), so
// split each sentence across 2 CTAs (100 words each): grid 4096 raises warp
// fill and concurrent load streams. Partials go to __device__ scratch; a tiny
// second kernel combines halves and divides by the total count.

#define B_DIM 2048
#define S_DIM 200
#define HALF_S 100
#define VDIM  75      // 300 floats = 75 float4 (1200 B row)
#define NTHREADS 96

__device__ float4 g_partial[2 * B_DIM * VDIM];   // 4096 x 75 float4 (4.9 MB)
__device__ int    g_count[2 * B_DIM];

__device__ __forceinline__ bool f4_nz(float4 v) {
    // nonzero iff any component != 0 (sign bit cleared so -0.0f counts as zero)
    unsigned a = __float_as_uint(v.x) | __float_as_uint(v.y);
    unsigned b = __float_as_uint(v.z) | __float_as_uint(v.w);
    return ((a | b) & 0x7fffffffu) != 0u;
}

__global__ __launch_bounds__(NTHREADS)
void partial_kernel(const float4* __restrict__ in) {
    __shared__ unsigned char flags[HALF_S];

    const int item = blockIdx.x;          // 0..4095
    const int b = item >> 1;
    const int h = item & 1;
    const int t = threadIdx.x;
    const bool active = (t < VDIM);

    for (int i = t; i < HALF_S; i += NTHREADS) flags[i] = 0;
    __syncthreads();

    const float4* __restrict__ row =
        in + (size_t)b * (S_DIM * VDIM) + (size_t)h * (HALF_S * VDIM);

    float4 acc = make_float4(0.f, 0.f, 0.f, 0.f);

    #pragma unroll 4
    for (int s = 0; s < HALF_S; ++s) {
        float4 v = make_float4(0.f, 0.f, 0.f, 0.f);
        if (active) v = row[s * VDIM + t];
        acc.x += v.x; acc.y += v.y; acc.z += v.z; acc.w += v.w;

        unsigned m = __ballot_sync(0xffffffffu, f4_nz(v));
        if (((t & 31) == 0) && m) flags[s] = 1;   // benign race, same value
    }
    __syncthreads();

    if (t < 32) {
        int c = 0;
        #pragma unroll
        for (int i = 0; i < HALF_S; i += 32)      // 100 = 3*32 + 4
            if (i + t < HALF_S) c += (int)flags[i + t];
        c = __reduce_add_sync(0xffffffffu, c);
        if (t == 0) g_count[item] = c;
    }

    if (active) g_partial[(size_t)item * VDIM + t] = acc;
}

__global__ __launch_bounds__(NTHREADS)
void combine_kernel(float4* __restrict__ out) {
    const int b = blockIdx.x;
    const int t = threadIdx.x;
    if (t >= VDIM) return;

    const int c = g_count[2 * b] + g_count[2 * b + 1];   // >= 1 guaranteed
    const float ic = 1.0f / (float)c;

    float4 p0 = g_partial[(size_t)(2 * b) * VDIM + t];
    float4 p1 = g_partial[(size_t)(2 * b + 1) * VDIM + t];

    out[(size_t)b * VDIM + t] = make_float4((p0.x + p1.x) * ic,
                                            (p0.y + p1.y) * ic,
                                            (p0.z + p1.z) * ic,
                                            (p0.w + p1.w) * ic);
}

extern "C" void kernel_launch(void* const* d_in, const int* in_sizes, int n_in,
                              void* d_out, int out_size) {
    (void)in_sizes; (void)n_in; (void)out_size;
    const float4* in = (const float4*)d_in[0];
    float4* out = (float4*)d_out;
    partial_kernel<<<2 * B_DIM, NTHREADS>>>(in);
    combine_kernel<<<B_DIM, NTHREADS>>>(out);
}

// round 4
// speedup vs baseline: 1.0714x; 1.0714x over previous
#include <cuda_runtime.h>
#include <cuda_bf16.h>

// word_vecs [B=2048, S=200, D=300] fp32 -> masked mean over S -> [B, D].
// All-zero (masked) words contribute 0 to the sum, so the sum needs no mask;
// only the count does. Count: per-word warp ballot -> benign-race flag write
// (same structure as the 78.0us R1 winner), with deeper unroll for MLP and an
// integer nonzero test (sign bit cleared so -0.0f padding counts as zero).

#define B_DIM 2048
#define S_DIM 200
#define VDIM  75      // 300 floats = 75 float4 (1200 B row, 16B-aligned)
#define NTHREADS 96

__device__ __forceinline__ bool f4_nz(float4 v) {
    unsigned a = __float_as_uint(v.x) | __float_as_uint(v.y);
    unsigned b = __float_as_uint(v.z) | __float_as_uint(v.w);
    return ((a | b) & 0x7fffffffu) != 0u;
}

__global__ __launch_bounds__(NTHREADS)
void sentence_rep_kernel(const float4* __restrict__ in, float4* __restrict__ out) {
    __shared__ unsigned char flags[S_DIM];
    __shared__ float inv_count;

    const int b = blockIdx.x;
    const int t = threadIdx.x;
    const bool active = (t < VDIM);
    const int lane = t & 31;

    for (int i = t; i < S_DIM; i += NTHREADS) flags[i] = 0;
    __syncthreads();

    const float4* __restrict__ p = in + (size_t)b * (S_DIM * VDIM) + t;

    float4 acc = make_float4(0.f, 0.f, 0.f, 0.f);

    #pragma unroll 8
    for (int s = 0; s < S_DIM; ++s) {
        float4 v = make_float4(0.f, 0.f, 0.f, 0.f);
        if (active) v = p[s * VDIM];
        acc.x += v.x; acc.y += v.y; acc.z += v.z; acc.w += v.w;

        unsigned m = __ballot_sync(0xffffffffu, f4_nz(v));
        if ((lane == 0) && m) flags[s] = 1;   // benign race: same value
    }
    __syncthreads();

    if (t < 32) {
        int c = 0;
        #pragma unroll
        for (int i = 0; i < S_DIM; i += 32)    // 200 = 6*32 + 8
            if (i + t < S_DIM) c += (int)flags[i + t];
        c = __reduce_add_sync(0xffffffffu, c);
        if (t == 0) inv_count = 1.0f / (float)c;   // count >= 1 guaranteed
    }
    __syncthreads();

    if (active) {
        const float ic = inv_count;
        out[(size_t)b * VDIM + t] =
            make_float4(acc.x * ic, acc.y * ic, acc.z * ic, acc.w * ic);
    }
}

extern "C" void kernel_launch(void* const* d_in, const int* in_sizes, int n_in,
                              void* d_out, int out_size) {
    (void)in_sizes; (void)n_in; (void)out_size;
    const float4* in = (const float4*)d_in[0];
    float4* out = (float4*)d_out;
    sentence_rep_kernel<<<B_DIM, NTHREADS>>>(in, out);
}

// round 5
// speedup vs baseline: 1.1867x; 1.1075x over previous
#include <cuda_runtime.h>
#include <cuda_bf16.h>

// Problem: word_vecs [B=2048, S=200, D=300] fp32 -> masked mean over S -> [B, D].
// A masked (all-zero) word contributes 0 to the sum, so the sum needs no mask;
// only the count does. This is byte-for-byte the R1 winner (78.0us) with one
// isolated change: __ldcs streaming loads (read-once data, evict-first).

#define B_DIM 2048
#define S_DIM 200
#define D_DIM 300
#define VDIM  75   // 300 floats = 75 float4 per word (1200 B, 16B-aligned stride)
#define NTHREADS 96

__global__ __launch_bounds__(NTHREADS)
void sentence_rep_kernel(const float4* __restrict__ in, float4* __restrict__ out) {
    __shared__ unsigned char flags[S_DIM];
    __shared__ float inv_count;

    const int b = blockIdx.x;
    const int t = threadIdx.x;
    const bool active = (t < VDIM);

    // zero the per-word flags
    for (int i = t; i < S_DIM; i += NTHREADS) flags[i] = 0;
    __syncthreads();

    const float4* __restrict__ row = in + (size_t)b * (S_DIM * VDIM);

    float4 acc = make_float4(0.f, 0.f, 0.f, 0.f);

    #pragma unroll 4
    for (int s = 0; s < S_DIM; ++s) {
        float4 v = make_float4(0.f, 0.f, 0.f, 0.f);
        if (active) v = __ldcs(&row[s * VDIM + t]);
        acc.x += v.x; acc.y += v.y; acc.z += v.z; acc.w += v.w;

        // per-word any-nonzero predicate (benign-race write of the same value)
        bool nz = (v.x != 0.f) || (v.y != 0.f) || (v.z != 0.f) || (v.w != 0.f);
        unsigned m = __ballot_sync(0xffffffffu, nz);
        if (((t & 31) == 0) && m) flags[s] = 1;
    }
    __syncthreads();

    // warp 0 reduces the 200 flags -> count -> 1/count
    if (t < 32) {
        int c = 0;
        for (int i = t; i < S_DIM; i += 32) c += (int)flags[i];
        #pragma unroll
        for (int o = 16; o > 0; o >>= 1) c += __shfl_down_sync(0xffffffffu, c, o);
        if (t == 0) inv_count = 1.0f / (float)c;   // count >= 1 guaranteed
    }
    __syncthreads();

    if (active) {
        const float ic = inv_count;
        out[(size_t)b * VDIM + t] =
            make_float4(acc.x * ic, acc.y * ic, acc.z * ic, acc.w * ic);
    }
}

extern "C" void kernel_launch(void* const* d_in, const int* in_sizes, int n_in,
                              void* d_out, int out_size) {
    (void)in_sizes; (void)n_in; (void)out_size;
    const float4* in = (const float4*)d_in[0];
    float4* out = (float4*)d_out;
    sentence_rep_kernel<<<B_DIM, NTHREADS>>>(in, out);
}